// round 2
// baseline (speedup 1.0000x reference)
#include <cuda_runtime.h>
#include <cstdint>

#define TOKENS 40960          // B*N = 128*320
#define BATCH 128
#define NSEQ 320
#define TMT 64                // mt window
#define CDIM 768
#define QKVDIM 2304
#define NHEAD 12
#define DHEAD 64

// ---- scratch (device globals: allocation-free per harness rules) ----
__device__ float g_qkv[(size_t)TOKENS * QKVDIM];   // [token][3*768] : which*768 + h*64 + d
__device__ float g_attn[(size_t)TOKENS * CDIM];    // [token][h*64 + d]

// ============================================================================
// SGEMM: C[M,N] = A[M,K] * W[N,K]^T (+bias). K = 768. 128x128 block, 8x8/thread.
// GATHER: A row m comes from x1 if (m%320)<64 else x2 (same flat offset m*768).
// Software-pipelined: next k-slab prefetched into registers during FMA phase.
// ============================================================================
template<bool GATHER, bool BIAS>
__global__ void __launch_bounds__(256) sgemm_tn(
    const float* __restrict__ A1, const float* __restrict__ A2,
    const float* __restrict__ W,  const float* __restrict__ bias,
    float* __restrict__ C, int ldc)
{
    __shared__ float As[8][128];
    __shared__ float Bs[8][128];

    const int t  = threadIdx.x;
    const int lr = t >> 1;            // 0..127 row within tile
    const int lk = (t & 1) << 2;      // 0 or 4

    const int m = blockIdx.y * 128 + lr;
    const int j = blockIdx.x * 128 + lr;

    const float* aptr;
    if (GATHER) {
        const int n = m % NSEQ;
        aptr = (n < TMT ? A1 : A2) + (size_t)m * CDIM + lk;
    } else {
        aptr = A1 + (size_t)m * CDIM + lk;
    }
    const float* bptr = W + (size_t)j * CDIM + lk;

    const int ty = t >> 4, tx = t & 15;

    float acc[8][8];
    #pragma unroll
    for (int i = 0; i < 8; i++)
        #pragma unroll
        for (int jj = 0; jj < 8; jj++) acc[i][jj] = 0.f;

    // prologue prefetch
    float4 av = *reinterpret_cast<const float4*>(aptr);
    float4 bv = *reinterpret_cast<const float4*>(bptr);

    for (int k0 = 0; k0 < CDIM; k0 += 8) {
        As[lk+0][lr] = av.x; As[lk+1][lr] = av.y; As[lk+2][lr] = av.z; As[lk+3][lr] = av.w;
        Bs[lk+0][lr] = bv.x; Bs[lk+1][lr] = bv.y; Bs[lk+2][lr] = bv.z; Bs[lk+3][lr] = bv.w;
        __syncthreads();

        // prefetch next slab while computing on this one
        if (k0 + 8 < CDIM) {
            av = *reinterpret_cast<const float4*>(aptr + k0 + 8);
            bv = *reinterpret_cast<const float4*>(bptr + k0 + 8);
        }

        #pragma unroll
        for (int kk = 0; kk < 8; kk++) {
            float4 a0 = *reinterpret_cast<const float4*>(&As[kk][ty*8]);
            float4 a1 = *reinterpret_cast<const float4*>(&As[kk][ty*8+4]);
            float4 b0 = *reinterpret_cast<const float4*>(&Bs[kk][tx*8]);
            float4 b1 = *reinterpret_cast<const float4*>(&Bs[kk][tx*8+4]);
            float a[8] = {a0.x,a0.y,a0.z,a0.w,a1.x,a1.y,a1.z,a1.w};
            float b[8] = {b0.x,b0.y,b0.z,b0.w,b1.x,b1.y,b1.z,b1.w};
            #pragma unroll
            for (int i = 0; i < 8; i++)
                #pragma unroll
                for (int jj = 0; jj < 8; jj++)
                    acc[i][jj] = fmaf(a[i], b[jj], acc[i][jj]);
        }
        __syncthreads();
    }

    const int mBase = blockIdx.y * 128 + ty * 8;
    const int cBase = blockIdx.x * 128 + tx * 8;
    #pragma unroll
    for (int i = 0; i < 8; i++) {
        float* crow = C + (size_t)(mBase + i) * ldc + cBase;
        float v[8];
        #pragma unroll
        for (int jj = 0; jj < 8; jj++) {
            v[jj] = acc[i][jj];
            if (BIAS) v[jj] += bias[cBase + jj];
        }
        reinterpret_cast<float4*>(crow)[0] = make_float4(v[0],v[1],v[2],v[3]);
        reinterpret_cast<float4*>(crow)[1] = make_float4(v[4],v[5],v[6],v[7]);
    }
}

// ============================================================================
// Flash-style fp32 attention. grid = (5 qtiles, H, B), 256 threads.
// qtile 0  -> queries 0..63, keys 0..63   (mt path)
// qtile1-4 -> queries 64..319, keys 0..319 (s path)
// smem: sQT[d][68] (d-major), sKV (KT d-major / V j-major), sPT[j][68]
// ============================================================================
#define PITCH 68
__global__ void __launch_bounds__(256) attn_kernel()
{
    extern __shared__ float sm[];
    float* sQT = sm;                  // [64][PITCH] index: d*PITCH + i
    float* sKV = sm + 64 * PITCH;     // K: d*PITCH + j  | V: j*PITCH + d
    float* sPT = sm + 2 * 64 * PITCH; // j*PITCH + i

    const int qtile = blockIdx.x;
    const int h = blockIdx.y;
    const int b = blockIdx.z;
    const int t = threadIdx.x;
    const int ty = t >> 4, tx = t & 15;
    const int i0 = ty * 4;            // query rows owned
    const int d0 = tx * 4;            // cols owned (keys in S phase, dims in PV phase)

    const size_t tokBase = (size_t)b * NSEQ;
    const int lrow = t >> 2;          // 0..63 loader row
    const int lf4  = t & 3;

    // load Q (transposed to d-major)
    {
        const float* qrow = g_qkv + (tokBase + qtile*64 + lrow) * QKVDIM + h * DHEAD;
        #pragma unroll
        for (int rep = 0; rep < 4; rep++) {
            int dd = (lf4 + rep * 4) * 4;
            float4 v = *reinterpret_cast<const float4*>(qrow + dd);
            sQT[(dd+0)*PITCH + lrow] = v.x;
            sQT[(dd+1)*PITCH + lrow] = v.y;
            sQT[(dd+2)*PITCH + lrow] = v.z;
            sQT[(dd+3)*PITCH + lrow] = v.w;
        }
    }

    float accO[4][4];
    float mrow[4], lsum[4];
    const float NEGINF = __int_as_float(0xff800000);
    #pragma unroll
    for (int r = 0; r < 4; r++) {
        mrow[r] = NEGINF; lsum[r] = 0.f;
        #pragma unroll
        for (int c = 0; c < 4; c++) accO[r][c] = 0.f;
    }

    const int nkt = (qtile == 0) ? 1 : 5;
    for (int kt = 0; kt < nkt; kt++) {
        __syncthreads();   // prev V/P reads done (and Q stores visible on iter 0)
        // load K tile transposed (d-major)
        {
            const float* krow = g_qkv + (tokBase + kt*64 + lrow) * QKVDIM + CDIM + h * DHEAD;
            #pragma unroll
            for (int rep = 0; rep < 4; rep++) {
                int dd = (lf4 + rep * 4) * 4;
                float4 v = *reinterpret_cast<const float4*>(krow + dd);
                sKV[(dd+0)*PITCH + lrow] = v.x;
                sKV[(dd+1)*PITCH + lrow] = v.y;
                sKV[(dd+2)*PITCH + lrow] = v.z;
                sKV[(dd+3)*PITCH + lrow] = v.w;
            }
        }
        __syncthreads();

        // S = (Q K^T) * scale  — thread owns S[i0+r][d0+c]
        float s[4][4];
        #pragma unroll
        for (int r = 0; r < 4; r++)
            #pragma unroll
            for (int c = 0; c < 4; c++) s[r][c] = 0.f;
        #pragma unroll 4
        for (int d = 0; d < 64; d++) {
            float4 a = *reinterpret_cast<const float4*>(&sQT[d*PITCH + i0]);
            float4 bb = *reinterpret_cast<const float4*>(&sKV[d*PITCH + d0]);
            float av[4] = {a.x,a.y,a.z,a.w};
            float bv[4] = {bb.x,bb.y,bb.z,bb.w};
            #pragma unroll
            for (int r = 0; r < 4; r++)
                #pragma unroll
                for (int c = 0; c < 4; c++)
                    s[r][c] = fmaf(av[r], bv[c], s[r][c]);
        }

        // online softmax (rows reduced across the 16 tx lanes)
        #pragma unroll
        for (int r = 0; r < 4; r++) {
            #pragma unroll
            for (int c = 0; c < 4; c++) s[r][c] *= 0.125f;   // d^-0.5
            float mx = fmaxf(fmaxf(s[r][0], s[r][1]), fmaxf(s[r][2], s[r][3]));
            #pragma unroll
            for (int off = 8; off >= 1; off >>= 1)
                mx = fmaxf(mx, __shfl_xor_sync(0xffffffffu, mx, off));
            float mnew = fmaxf(mrow[r], mx);
            float corr = __expf(mrow[r] - mnew);
            float rs = 0.f;
            #pragma unroll
            for (int c = 0; c < 4; c++) {
                s[r][c] = __expf(s[r][c] - mnew);
                rs += s[r][c];
            }
            #pragma unroll
            for (int off = 8; off >= 1; off >>= 1)
                rs += __shfl_xor_sync(0xffffffffu, rs, off);
            lsum[r] = lsum[r] * corr + rs;
            #pragma unroll
            for (int c = 0; c < 4; c++) accO[r][c] *= corr;
            mrow[r] = mnew;
        }
        // store P transposed: sPT[j][i]
        #pragma unroll
        for (int r = 0; r < 4; r++)
            #pragma unroll
            for (int c = 0; c < 4; c++)
                sPT[(d0+c)*PITCH + (i0+r)] = s[r][c];

        __syncthreads();   // K reads done, P visible
        // load V tile (natural j-major)
        {
            const float* vrow = g_qkv + (tokBase + kt*64 + lrow) * QKVDIM + 2*CDIM + h * DHEAD;
            #pragma unroll
            for (int rep = 0; rep < 4; rep++) {
                int dd = (lf4 + rep * 4) * 4;
                float4 v = *reinterpret_cast<const float4*>(vrow + dd);
                *reinterpret_cast<float4*>(&sKV[lrow*PITCH + dd]) = v;
            }
        }
        __syncthreads();

        // O += P V — thread owns O[i0+r][d0+c]
        #pragma unroll 4
        for (int jj = 0; jj < 64; jj++) {
            float4 p = *reinterpret_cast<const float4*>(&sPT[jj*PITCH + i0]);
            float4 v = *reinterpret_cast<const float4*>(&sKV[jj*PITCH + d0]);
            float pv[4] = {p.x,p.y,p.z,p.w};
            float vv[4] = {v.x,v.y,v.z,v.w};
            #pragma unroll
            for (int r = 0; r < 4; r++)
                #pragma unroll
                for (int c = 0; c < 4; c++)
                    accO[r][c] = fmaf(pv[r], vv[c], accO[r][c]);
        }
    }

    // epilogue: normalize + write [token][h*64+d]
    #pragma unroll
    for (int r = 0; r < 4; r++) {
        float inv = 1.f / lsum[r];
        int n = qtile * 64 + i0 + r;
        float4 o = make_float4(accO[r][0]*inv, accO[r][1]*inv,
                               accO[r][2]*inv, accO[r][3]*inv);
        *reinterpret_cast<float4*>(g_attn + (tokBase + n) * CDIM + h * DHEAD + d0) = o;
    }
}

// ============================================================================
// launch
// ============================================================================
extern "C" void kernel_launch(void* const* d_in, const int* in_sizes, int n_in,
                              void* d_out, int out_size)
{
    const float* x1     = (const float*)d_in[0];
    const float* x2     = (const float*)d_in[1];
    const float* qkv_w  = (const float*)d_in[2];
    const float* proj_w = (const float*)d_in[3];
    const float* proj_b = (const float*)d_in[4];
    float* out = (float*)d_out;

    float* qkv;  cudaGetSymbolAddress((void**)&qkv,  g_qkv);
    float* attn; cudaGetSymbolAddress((void**)&attn, g_attn);

    const int smemAttn = 3 * 64 * PITCH * sizeof(float);   // 52224 B
    cudaFuncSetAttribute(attn_kernel, cudaFuncAttributeMaxDynamicSharedMemorySize, smemAttn);

    // 1) QKV = gather(x1,x2) @ qkv_w^T
    dim3 g1(QKVDIM / 128, TOKENS / 128);   // (18, 320)
    sgemm_tn<true, false><<<g1, 256>>>(x1, x2, qkv_w, nullptr, qkv, QKVDIM);

    // 2) attention
    dim3 g2(5, NHEAD, BATCH);              // (5, 12, 128)
    attn_kernel<<<g2, 256, smemAttn>>>();

    // 3) out = attn @ proj_w^T + proj_b
    dim3 g3(CDIM / 128, TOKENS / 128);     // (6, 320)
    sgemm_tn<false, true><<<g3, 256>>>(attn, nullptr, proj_w, proj_b, out, CDIM);
}

// round 5
// speedup vs baseline: 1.5032x; 1.5032x over previous
#include <cuda_runtime.h>
#include <cuda_bf16.h>
#include <cstdint>

#define TOKENS 40960          // B*N = 128*320
#define BATCH 128
#define NSEQ 320
#define TMT 64                // mt window
#define CDIM 768
#define QKVDIM 2304
#define NHEAD 12
#define DHEAD 64

// ---- scratch (device globals: allocation-free per harness rules) ----
__device__ float g_qkv[(size_t)TOKENS * QKVDIM];   // [token][3*768] : which*768 + h*64 + d
__device__ float g_attn[(size_t)TOKENS * CDIM];    // [token][h*64 + d]

// ============================================================================
// bf16x3 split tensor-core GEMM: C[M,N] = A[M,K] * W[N,K]^T (+bias), fp32 I/O.
// Each fp32 split into hi+lo bf16; C += Ah*Bh + Al*Bh + Ah*Bl (fp32 accum).
// 128x128x32 block tile, 8 warps (32x64 warp tile), double-buffered smem.
// ============================================================================
#define BM 128
#define BN 128
#define BK 32
#define PIT 40                 // bf16 pitch (32 + 8 pad): LDSM & STS conflict-free
#define TILE_E (128 * PIT)     // elems per stage per region

__device__ __forceinline__ void ldm_x4(uint32_t* r, uint32_t addr) {
    asm volatile("ldmatrix.sync.aligned.m8n8.x4.shared.b16 {%0,%1,%2,%3}, [%4];"
        : "=r"(r[0]), "=r"(r[1]), "=r"(r[2]), "=r"(r[3]) : "r"(addr));
}
__device__ __forceinline__ void mma16816(float* c, const uint32_t* a, const uint32_t* b) {
    asm volatile("mma.sync.aligned.m16n8k16.row.col.f32.bf16.bf16.f32 "
        "{%0,%1,%2,%3}, {%4,%5,%6,%7}, {%8,%9}, {%0,%1,%2,%3};"
        : "+f"(c[0]), "+f"(c[1]), "+f"(c[2]), "+f"(c[3])
        : "r"(a[0]), "r"(a[1]), "r"(a[2]), "r"(a[3]), "r"(b[0]), "r"(b[1]));
}
__device__ __forceinline__ uint32_t packbf2(__nv_bfloat16 a, __nv_bfloat16 b) {
    __nv_bfloat162 t; t.x = a; t.y = b;
    return *reinterpret_cast<uint32_t*>(&t);
}
// split float4 (4 consecutive k) into hi/lo bf16x2 pairs
__device__ __forceinline__ void split4(float4 v, uint32_t* h, uint32_t* l) {
    __nv_bfloat16 h0 = __float2bfloat16_rn(v.x);
    __nv_bfloat16 h1 = __float2bfloat16_rn(v.y);
    __nv_bfloat16 h2 = __float2bfloat16_rn(v.z);
    __nv_bfloat16 h3 = __float2bfloat16_rn(v.w);
    __nv_bfloat16 l0 = __float2bfloat16_rn(v.x - __bfloat162float(h0));
    __nv_bfloat16 l1 = __float2bfloat16_rn(v.y - __bfloat162float(h1));
    __nv_bfloat16 l2 = __float2bfloat16_rn(v.z - __bfloat162float(h2));
    __nv_bfloat16 l3 = __float2bfloat16_rn(v.w - __bfloat162float(h3));
    h[0] = packbf2(h0, h1); h[1] = packbf2(h2, h3);
    l[0] = packbf2(l0, l1); l[1] = packbf2(l2, l3);
}

// split 4x float4 (A and B k-slabs) and store hi/lo to the 4 smem regions
__device__ __forceinline__ void store_stage(
    __nv_bfloat16* sAh, __nv_bfloat16* sAl,
    __nv_bfloat16* sBh, __nv_bfloat16* sBl,
    const float4* pa, const float4* pb, int be)
{
    uint32_t ha[8], la[8], hb[8], lb[8];
    #pragma unroll
    for (int i = 0; i < 4; i++) {
        split4(pa[i], &ha[2*i], &la[2*i]);
        split4(pb[i], &hb[2*i], &lb[2*i]);
    }
    *reinterpret_cast<uint4*>(sAh + be)     = make_uint4(ha[0],ha[1],ha[2],ha[3]);
    *reinterpret_cast<uint4*>(sAh + be + 8) = make_uint4(ha[4],ha[5],ha[6],ha[7]);
    *reinterpret_cast<uint4*>(sAl + be)     = make_uint4(la[0],la[1],la[2],la[3]);
    *reinterpret_cast<uint4*>(sAl + be + 8) = make_uint4(la[4],la[5],la[6],la[7]);
    *reinterpret_cast<uint4*>(sBh + be)     = make_uint4(hb[0],hb[1],hb[2],hb[3]);
    *reinterpret_cast<uint4*>(sBh + be + 8) = make_uint4(hb[4],hb[5],hb[6],hb[7]);
    *reinterpret_cast<uint4*>(sBl + be)     = make_uint4(lb[0],lb[1],lb[2],lb[3]);
    *reinterpret_cast<uint4*>(sBl + be + 8) = make_uint4(lb[4],lb[5],lb[6],lb[7]);
}

template<bool GATHER, bool BIAS>
__global__ void __launch_bounds__(256) mma_gemm(
    const float* __restrict__ A1, const float* __restrict__ A2,
    const float* __restrict__ W,  const float* __restrict__ bias,
    float* __restrict__ C, int ldc)
{
    extern __shared__ __nv_bfloat16 sm[];
    __nv_bfloat16* sAh = sm;                 // [2][128][PIT]
    __nv_bfloat16* sAl = sm + 2 * TILE_E;
    __nv_bfloat16* sBh = sm + 4 * TILE_E;
    __nv_bfloat16* sBl = sm + 6 * TILE_E;
    const uint32_t sbase = (uint32_t)__cvta_generic_to_shared(sm);

    const int t    = threadIdx.x;
    const int lane = t & 31, wid = t >> 5;
    const int wm   = (wid & 3) * 32;         // warp M base
    const int wn   = (wid >> 2) * 64;        // warp N base

    // loader mapping: row = t&127, k-half = (t>>7)*16
    const int lrow = t & 127;
    const int lkh  = (t >> 7) * 16;

    const int mRow = blockIdx.y * BM + lrow;
    const float* aRow;
    if (GATHER) {
        const int n = mRow % NSEQ;
        aRow = (n < TMT ? A1 : A2) + (size_t)mRow * CDIM + lkh;
    } else {
        aRow = A1 + (size_t)mRow * CDIM + lkh;
    }
    const float* bRow = W + (size_t)(blockIdx.x * BN + lrow) * CDIM + lkh;

    // ldmatrix lane-constant offsets (elements)
    const int r8 = lane & 7, sub = lane >> 3;
    const int offA = (r8 + (sub & 1) * 8) * PIT + (sub >> 1) * 8;   // A operand
    const int offB = (r8 + (sub >> 1) * 8) * PIT + (sub & 1) * 8;   // B operand

    float acc[2][8][4];
    #pragma unroll
    for (int mi = 0; mi < 2; mi++)
        #pragma unroll
        for (int nt = 0; nt < 8; nt++)
            #pragma unroll
            for (int q = 0; q < 4; q++) acc[mi][nt][q] = 0.f;

    float4 pa[4], pb[4];

    // ---- prologue: load + store stage 0 ----
    #pragma unroll
    for (int i = 0; i < 4; i++) {
        pa[i] = *reinterpret_cast<const float4*>(aRow + i * 4);
        pb[i] = *reinterpret_cast<const float4*>(bRow + i * 4);
    }
    store_stage(sAh, sAl, sBh, sBl, pa, pb, lrow * PIT + lkh);
    __syncthreads();

    const int NIT = CDIM / BK;   // 24
    for (int it = 0; it < NIT; it++) {
        const int cur = it & 1;

        // prefetch next k-slab into registers
        if (it + 1 < NIT) {
            const int k0 = (it + 1) * BK;
            #pragma unroll
            for (int i = 0; i < 4; i++) {
                pa[i] = *reinterpret_cast<const float4*>(aRow + k0 + i * 4);
                pb[i] = *reinterpret_cast<const float4*>(bRow + k0 + i * 4);
            }
        }

        // ---- compute on stage cur ----
        #pragma unroll
        for (int kk = 0; kk < 2; kk++) {
            const int k16 = kk * 16;
            uint32_t fAh[2][4], fAl[2][4], fBh[4][4], fBl[4][4];
            #pragma unroll
            for (int mi = 0; mi < 2; mi++) {
                const int e = cur * TILE_E + (wm + mi * 16) * PIT + k16 + offA;
                ldm_x4(fAh[mi], sbase + (0 * TILE_E + e) * 2);
                ldm_x4(fAl[mi], sbase + (2 * TILE_E + e) * 2);
            }
            #pragma unroll
            for (int np = 0; np < 4; np++) {
                const int e = cur * TILE_E + (wn + np * 16) * PIT + k16 + offB;
                ldm_x4(fBh[np], sbase + (4 * TILE_E + e) * 2);
                ldm_x4(fBl[np], sbase + (6 * TILE_E + e) * 2);
            }
            #pragma unroll
            for (int mi = 0; mi < 2; mi++)
                #pragma unroll
                for (int nt = 0; nt < 8; nt++) {
                    float* c = acc[mi][nt];
                    const uint32_t* bh = &fBh[nt >> 1][(nt & 1) * 2];
                    const uint32_t* bl = &fBl[nt >> 1][(nt & 1) * 2];
                    mma16816(c, fAh[mi], bh);
                    mma16816(c, fAl[mi], bh);
                    mma16816(c, fAh[mi], bl);
                }
        }

        // ---- convert + store next stage ----
        if (it + 1 < NIT) {
            store_stage(sAh, sAl, sBh, sBl, pa, pb,
                        (cur ^ 1) * TILE_E + lrow * PIT + lkh);
        }
        __syncthreads();
    }

    // ---- epilogue ----
    const int mB  = blockIdx.y * BM + wm;
    const int nB  = blockIdx.x * BN + wn;
    const int lr4 = lane >> 2, lc2 = (lane & 3) * 2;
    #pragma unroll
    for (int mi = 0; mi < 2; mi++)
        #pragma unroll
        for (int nt = 0; nt < 8; nt++) {
            const int col = nB + nt * 8 + lc2;
            float b0 = 0.f, b1 = 0.f;
            if (BIAS) { b0 = bias[col]; b1 = bias[col + 1]; }
            const int row0 = mB + mi * 16 + lr4;
            *reinterpret_cast<float2*>(C + (size_t)row0 * ldc + col) =
                make_float2(acc[mi][nt][0] + b0, acc[mi][nt][1] + b1);
            *reinterpret_cast<float2*>(C + (size_t)(row0 + 8) * ldc + col) =
                make_float2(acc[mi][nt][2] + b0, acc[mi][nt][3] + b1);
        }
}

// ============================================================================
// Flash-style fp32 attention (unchanged, passing). grid = (5, H, B), 256 thr.
// ============================================================================
#define PITCH 68
__global__ void __launch_bounds__(256) attn_kernel()
{
    extern __shared__ float smf[];
    float* sQT = smf;                  // [64][PITCH] d-major
    float* sKV = smf + 64 * PITCH;     // K: d-major | V: j-major
    float* sPT = smf + 2 * 64 * PITCH; // j*PITCH + i

    const int qtile = blockIdx.x;
    const int h = blockIdx.y;
    const int b = blockIdx.z;
    const int t = threadIdx.x;
    const int ty = t >> 4, tx = t & 15;
    const int i0 = ty * 4;
    const int d0 = tx * 4;

    const size_t tokBase = (size_t)b * NSEQ;
    const int lrow = t >> 2;
    const int lf4  = t & 3;

    {
        const float* qrow = g_qkv + (tokBase + qtile*64 + lrow) * QKVDIM + h * DHEAD;
        #pragma unroll
        for (int rep = 0; rep < 4; rep++) {
            int dd = (lf4 + rep * 4) * 4;
            float4 v = *reinterpret_cast<const float4*>(qrow + dd);
            sQT[(dd+0)*PITCH + lrow] = v.x;
            sQT[(dd+1)*PITCH + lrow] = v.y;
            sQT[(dd+2)*PITCH + lrow] = v.z;
            sQT[(dd+3)*PITCH + lrow] = v.w;
        }
    }

    float accO[4][4];
    float mrow[4], lsum[4];
    const float NEGINF = __int_as_float(0xff800000);
    #pragma unroll
    for (int r = 0; r < 4; r++) {
        mrow[r] = NEGINF; lsum[r] = 0.f;
        #pragma unroll
        for (int c = 0; c < 4; c++) accO[r][c] = 0.f;
    }

    const int nkt = (qtile == 0) ? 1 : 5;
    for (int kt = 0; kt < nkt; kt++) {
        __syncthreads();
        {
            const float* krow = g_qkv + (tokBase + kt*64 + lrow) * QKVDIM + CDIM + h * DHEAD;
            #pragma unroll
            for (int rep = 0; rep < 4; rep++) {
                int dd = (lf4 + rep * 4) * 4;
                float4 v = *reinterpret_cast<const float4*>(krow + dd);
                sKV[(dd+0)*PITCH + lrow] = v.x;
                sKV[(dd+1)*PITCH + lrow] = v.y;
                sKV[(dd+2)*PITCH + lrow] = v.z;
                sKV[(dd+3)*PITCH + lrow] = v.w;
            }
        }
        __syncthreads();

        float s[4][4];
        #pragma unroll
        for (int r = 0; r < 4; r++)
            #pragma unroll
            for (int c = 0; c < 4; c++) s[r][c] = 0.f;
        #pragma unroll 4
        for (int d = 0; d < 64; d++) {
            float4 a  = *reinterpret_cast<const float4*>(&sQT[d*PITCH + i0]);
            float4 bb = *reinterpret_cast<const float4*>(&sKV[d*PITCH + d0]);
            float av[4] = {a.x,a.y,a.z,a.w};
            float bv[4] = {bb.x,bb.y,bb.z,bb.w};
            #pragma unroll
            for (int r = 0; r < 4; r++)
                #pragma unroll
                for (int c = 0; c < 4; c++)
                    s[r][c] = fmaf(av[r], bv[c], s[r][c]);
        }

        #pragma unroll
        for (int r = 0; r < 4; r++) {
            #pragma unroll
            for (int c = 0; c < 4; c++) s[r][c] *= 0.125f;
            float mx = fmaxf(fmaxf(s[r][0], s[r][1]), fmaxf(s[r][2], s[r][3]));
            #pragma unroll
            for (int off = 8; off >= 1; off >>= 1)
                mx = fmaxf(mx, __shfl_xor_sync(0xffffffffu, mx, off));
            float mnew = fmaxf(mrow[r], mx);
            float corr = __expf(mrow[r] - mnew);
            float rs = 0.f;
            #pragma unroll
            for (int c = 0; c < 4; c++) {
                s[r][c] = __expf(s[r][c] - mnew);
                rs += s[r][c];
            }
            #pragma unroll
            for (int off = 8; off >= 1; off >>= 1)
                rs += __shfl_xor_sync(0xffffffffu, rs, off);
            lsum[r] = lsum[r] * corr + rs;
            #pragma unroll
            for (int c = 0; c < 4; c++) accO[r][c] *= corr;
            mrow[r] = mnew;
        }
        #pragma unroll
        for (int r = 0; r < 4; r++)
            #pragma unroll
            for (int c = 0; c < 4; c++)
                sPT[(d0+c)*PITCH + (i0+r)] = s[r][c];

        __syncthreads();
        {
            const float* vrow = g_qkv + (tokBase + kt*64 + lrow) * QKVDIM + 2*CDIM + h * DHEAD;
            #pragma unroll
            for (int rep = 0; rep < 4; rep++) {
                int dd = (lf4 + rep * 4) * 4;
                float4 v = *reinterpret_cast<const float4*>(vrow + dd);
                *reinterpret_cast<float4*>(&sKV[lrow*PITCH + dd]) = v;
            }
        }
        __syncthreads();

        #pragma unroll 4
        for (int jj = 0; jj < 64; jj++) {
            float4 p = *reinterpret_cast<const float4*>(&sPT[jj*PITCH + i0]);
            float4 v = *reinterpret_cast<const float4*>(&sKV[jj*PITCH + d0]);
            float pv[4] = {p.x,p.y,p.z,p.w};
            float vv[4] = {v.x,v.y,v.z,v.w};
            #pragma unroll
            for (int r = 0; r < 4; r++)
                #pragma unroll
                for (int c = 0; c < 4; c++)
                    accO[r][c] = fmaf(pv[r], vv[c], accO[r][c]);
        }
    }

    #pragma unroll
    for (int r = 0; r < 4; r++) {
        float inv = 1.f / lsum[r];
        int n = qtile * 64 + i0 + r;
        float4 o = make_float4(accO[r][0]*inv, accO[r][1]*inv,
                               accO[r][2]*inv, accO[r][3]*inv);
        *reinterpret_cast<float4*>(g_attn + (tokBase + n) * CDIM + h * DHEAD + d0) = o;
    }
}

// ============================================================================
// launch
// ============================================================================
extern "C" void kernel_launch(void* const* d_in, const int* in_sizes, int n_in,
                              void* d_out, int out_size)
{
    const float* x1     = (const float*)d_in[0];
    const float* x2     = (const float*)d_in[1];
    const float* qkv_w  = (const float*)d_in[2];
    const float* proj_w = (const float*)d_in[3];
    const float* proj_b = (const float*)d_in[4];
    float* out = (float*)d_out;

    float* qkv;  cudaGetSymbolAddress((void**)&qkv,  g_qkv);
    float* attn; cudaGetSymbolAddress((void**)&attn, g_attn);

    const int smemGemm = 8 * TILE_E * sizeof(__nv_bfloat16);   // 81920 B
    const int smemAttn = 3 * 64 * PITCH * sizeof(float);       // 52224 B
    cudaFuncSetAttribute(mma_gemm<true,  false>, cudaFuncAttributeMaxDynamicSharedMemorySize, smemGemm);
    cudaFuncSetAttribute(mma_gemm<false, true>,  cudaFuncAttributeMaxDynamicSharedMemorySize, smemGemm);
    cudaFuncSetAttribute(attn_kernel, cudaFuncAttributeMaxDynamicSharedMemorySize, smemAttn);

    // 1) QKV = gather(x1,x2) @ qkv_w^T
    dim3 g1(QKVDIM / BN, TOKENS / BM);     // (18, 320)
    mma_gemm<true, false><<<g1, 256, smemGemm>>>(x1, x2, qkv_w, nullptr, qkv, QKVDIM);

    // 2) attention
    dim3 g2(5, NHEAD, BATCH);              // (5, 12, 128)
    attn_kernel<<<g2, 256, smemAttn>>>();

    // 3) out = attn @ proj_w^T + proj_b
    dim3 g3(CDIM / BN, TOKENS / BM);       // (6, 320)
    mma_gemm<false, true><<<g3, 256, smemGemm>>>(attn, nullptr, proj_w, proj_b, out, CDIM);
}